// round 13
// baseline (speedup 1.0000x reference)
#include <cuda_runtime.h>

// Problem constants (shapes fixed by the dataset)
#define NB   16
#define C    256
#define HW   16384          // 128*128
#define CLS  9
#define P    (NB*HW)        // 262144 pixels
#define NT   256
#define NBLK_ARG ((P/2)/NT) // 512 argmax blocks (2 px/thread)
#define NPLANE (NB*C)       // 4096 (n,c) planes

// Scratch (no allocation; every word fully overwritten each replay)
__device__ unsigned char g_labels[P];
__device__ int           g_cnt_part[NBLK_ARG * CLS];
__device__ float         g_part[NPLANE * CLS];

// ---------------------------------------------------------------------------
// 1) per-pixel argmax (float2, 2 px/thread) -> labels + per-block counts
// ---------------------------------------------------------------------------
__global__ void __launch_bounds__(NT) argmax_kernel(const float* __restrict__ logit) {
    __shared__ int s_cnt[CLS];
    const int tid = threadIdx.x;
    if (tid < CLS) s_cnt[tid] = 0;
    __syncthreads();

    const int g   = blockIdx.x * NT + tid;   // float2-group index
    const int n   = g >> 13;                 // g / (HW/2)
    const int hw2 = g & 8191;

    const float2* lp = (const float2*)logit;
    float2 best = lp[(size_t)(n*CLS + 0) * (HW/2) + hw2];
    int lx = 0, ly = 0;
    #pragma unroll
    for (int cls = 1; cls < CLS; cls++) {
        float2 v = lp[(size_t)(n*CLS + cls) * (HW/2) + hw2];
        if (v.x > best.x) { best.x = v.x; lx = cls; }
        if (v.y > best.y) { best.y = v.y; ly = cls; }
    }
    g_labels[2*g]   = (unsigned char)lx;
    g_labels[2*g+1] = (unsigned char)ly;

    atomicAdd(&s_cnt[lx], 1);
    atomicAdd(&s_cnt[ly], 1);
    __syncthreads();
    if (tid < CLS) g_cnt_part[blockIdx.x * CLS + tid] = s_cnt[tid];
}

// ---------------------------------------------------------------------------
// 2) accumulate: one block per (n,c) plane (4096 blocks, 16 iters — the
//    best-measured structure). The smem RMW is now ATOMS (fire-and-forget):
//    no LDS->FADD->STS latency chain, no compiler ordering constraints.
//    Per-lane columns => every warp atomic hits 32 distinct banks (fast path).
//    Each slot touched by exactly one thread => deterministic FP order.
// ---------------------------------------------------------------------------
__global__ void __launch_bounds__(NT) accum_kernel(const float* __restrict__ feat) {
    __shared__ float acc[CLS * NT];
    __shared__ float s_warp[CLS * 8];
    const int tid = threadIdx.x;
    #pragma unroll
    for (int l = 0; l < CLS; l++) acc[l*NT + tid] = 0.0f;
    __syncthreads();

    const int nc = blockIdx.x;        // 0..NPLANE-1
    const int n  = nc >> 8;           // nc / C

    const float4* fp = (const float4*)feat     + (size_t)nc * (HW/4);
    const uchar4* lp = (const uchar4*)g_labels + (size_t)n  * (HW/4);

    #pragma unroll
    for (int k = 0; k < (HW/4)/NT; k++) {   // 16 iterations
        const int i = tid + k*NT;
        float4 v = fp[i];
        uchar4 l = lp[i];
        atomicAdd(&acc[l.x*NT + tid], v.x);
        atomicAdd(&acc[l.y*NT + tid], v.y);
        atomicAdd(&acc[l.z*NT + tid], v.z);
        atomicAdd(&acc[l.w*NT + tid], v.w);
    }
    __syncthreads();

    // butterfly reduce all 9 classes
    float s[CLS];
    #pragma unroll
    for (int c = 0; c < CLS; c++) s[c] = acc[c*NT + tid];
    #pragma unroll
    for (int off = 16; off > 0; off >>= 1) {
        #pragma unroll
        for (int c = 0; c < CLS; c++)
            s[c] += __shfl_xor_sync(0xFFFFFFFFu, s[c], off);
    }
    const int warp = tid >> 5, lane = tid & 31;
    if (lane == 0) {
        #pragma unroll
        for (int c = 0; c < CLS; c++) s_warp[c*8 + warp] = s[c];
    }
    __syncthreads();

    if (tid < CLS) {
        float t = 0.0f;
        #pragma unroll
        for (int w = 0; w < 8; w++) t += s_warp[tid*8 + w];
        g_part[nc*CLS + tid] = t;     // plain store, private slot
    }
}

// ---------------------------------------------------------------------------
// 3) finalize: 9 blocks x 256 threads. Each thread owns one (ch,cls) pair:
//    sum 16 L2-resident partials, scale by 1/count, broadcast over batch.
// ---------------------------------------------------------------------------
__global__ void __launch_bounds__(NT) out_kernel(float* __restrict__ out) {
    __shared__ float s_wcnt[CLS * 8];
    __shared__ float s_inv[CLS];
    const int tid = threadIdx.x;

    float c[CLS];
    #pragma unroll
    for (int l = 0; l < CLS; l++)
        c[l] = (float)g_cnt_part[tid*CLS + l]
             + (float)g_cnt_part[(tid + NT)*CLS + l];
    #pragma unroll
    for (int off = 16; off > 0; off >>= 1) {
        #pragma unroll
        for (int l = 0; l < CLS; l++)
            c[l] += __shfl_xor_sync(0xFFFFFFFFu, c[l], off);
    }
    const int warp = tid >> 5, lane = tid & 31;
    if (lane == 0) {
        #pragma unroll
        for (int l = 0; l < CLS; l++) s_wcnt[l*8 + warp] = c[l];
    }
    __syncthreads();
    if (tid < CLS) {
        float s = 0.0f;
        #pragma unroll
        for (int w = 0; w < 8; w++) s += s_wcnt[tid*8 + w];
        s_inv[tid] = 1.0f / fmaxf(s, 1.0f);
    }
    __syncthreads();

    const int idx = blockIdx.x * NT + tid;   // 0..2303 (C*CLS)
    if (idx >= C*CLS) return;
    const int ch  = idx / CLS;
    const int cls = idx - ch*CLS;

    float s = 0.0f;
    #pragma unroll
    for (int n = 0; n < NB; n++)
        s += g_part[(n*C + ch)*CLS + cls];
    const float val = s * s_inv[cls];
    #pragma unroll
    for (int n = 0; n < NB; n++)
        out[n*(C*CLS) + idx] = val;
}

// ---------------------------------------------------------------------------
extern "C" void kernel_launch(void* const* d_in, const int* in_sizes, int n_in,
                              void* d_out, int out_size) {
    const float* feat  = (const float*)d_in[0];
    const float* logit = (const float*)d_in[1];
    float* out = (float*)d_out;

    argmax_kernel<<<NBLK_ARG, NT>>>(logit);          // 512 blocks
    accum_kernel<<<NPLANE, NT>>>(feat);              // 4096 blocks
    out_kernel<<<(C*CLS + NT - 1)/NT, NT>>>(out);    // 9 blocks
}